// round 2
// baseline (speedup 1.0000x reference)
#include <cuda_runtime.h>

#define NV 96
#define NNE 9216
#define LAT 256
#define OUTD 4656
#define ITERS 50

__device__ float g_p_mu[16][LAT];
__device__ float g_p_ls[16][LAT];
__device__ float g_p_y[16][LAT];
__device__ float g_mu[LAT];
__device__ float g_y[LAT];
__device__ float g_kl;
__device__ float g_out[OUTD];
__device__ float g_B[NNE];
__device__ float g_A[NNE];
__device__ float g_D[NNE];
__device__ float g_xf[NNE];
__device__ float g_M[2][NNE];
__device__ int   g_scale[64];
__device__ unsigned long long g_bar;
__device__ int   g_ind[NV];

// ---------- GEMV stage 1 ----------
__global__ void k_gemv1(const float* __restrict__ h, const float* __restrict__ Wmu,
                        const float* __restrict__ Wls) {
    __shared__ float sh[576];
    int c = blockIdx.x, mat = blockIdx.y, o = threadIdx.x;
    int k0 = c * 576;
    for (int kk = o; kk < 576; kk += 256) sh[kk] = h[k0 + kk];
    __syncthreads();
    const float* Wp = (mat ? Wls : Wmu) + (size_t)k0 * LAT + o;
    float acc = 0.f;
#pragma unroll 4
    for (int kk = 0; kk < 576; kk++) acc += sh[kk] * Wp[(size_t)kk * LAT];
    if (mat) g_p_ls[c][o] = acc; else g_p_mu[c][o] = acc;
}

__global__ void k_red1(const float* __restrict__ bmu, const float* __restrict__ bls) {
    __shared__ float rb[8];
    int o = threadIdx.x;
    float smu = bmu[o], sls = bls[o];
#pragma unroll
    for (int c = 0; c < 16; c++) { smu += g_p_mu[c][o]; sls += g_p_ls[c][o]; }
    g_mu[o] = smu;
    float v = 1.f + sls - smu * smu - expf(sls);
    for (int off = 16; off; off >>= 1) v += __shfl_down_sync(0xffffffffu, v, off);
    if ((o & 31) == 0) rb[o >> 5] = v;
    __syncthreads();
    if (o < 8) {
        v = rb[o];
        for (int off = 4; off; off >>= 1) v += __shfl_down_sync(0xffu, v, off);
        if (o == 0) g_kl = -0.5f * v / (float)NNE;
    }
}

// ---------- GEMV stage 2 ----------
__global__ void k_gemv2(const float* __restrict__ h, const float* __restrict__ Wd1) {
    __shared__ float sh[592];
    int c = blockIdx.x, o = threadIdx.x;
    int k0 = c * 592;
    for (int kk = o; kk < 592; kk += 256) {
        int k = k0 + kk;
        sh[kk] = (k < NNE) ? h[k] : g_mu[k - NNE];
    }
    __syncthreads();
    const float* Wp = Wd1 + (size_t)k0 * LAT + o;
    float acc = 0.f;
#pragma unroll 4
    for (int kk = 0; kk < 592; kk++) acc += sh[kk] * Wp[(size_t)kk * LAT];
    g_p_y[c][o] = acc;
}

__global__ void k_red2(const float* __restrict__ bd1) {
    int o = threadIdx.x;
    float s = bd1[o];
#pragma unroll
    for (int c = 0; c < 16; c++) s += g_p_y[c][o];
    g_y[o] = fmaxf(s, 0.f);
}

__global__ void k_out(const float* __restrict__ Wd2, const float* __restrict__ bd2) {
    __shared__ float ys[LAT];
    int t = threadIdx.x;
    ys[t] = g_y[t];
    __syncthreads();
    int o = blockIdx.x * 256 + t;
    if (o < OUTD) {
        float acc = bd2[o];
#pragma unroll 4
        for (int k = 0; k < LAT; k++) acc += ys[k] * Wd2[(size_t)k * OUTD + o];
        g_out[o] = 1.f / (1.f + expf(-acc));
    }
}

// ---------- setup: A, B, D, scale ----------
__global__ void k_setup(const float* __restrict__ adj) {
    __shared__ float recs[NV * 97];
    __shared__ float sd[NV], snf[NV], sdr[NV], snfr[NV];
    int i = threadIdx.x;  // 96
    float nfi = 0.f;
    for (int j = 0; j < NV; j++) nfi += adj[i * NV + j];
    sd[i] = adj[i * NV + i];
    snf[i] = nfi;
    float nfri = 0.f;
    for (int j = 0; j < NV; j++) {
        int a = min(i, j), b = max(i, j);
        float r = g_out[a * NV - (a * (a - 1)) / 2 + (b - a)];
        recs[i * 97 + j] = r;
        nfri += r;
    }
    sdr[i] = recs[i * 97 + i];
    snfr[i] = nfri;
    __syncthreads();
    float di = sd[i], dri = sdr[i], nfi2 = snf[i];
    for (int j = 0; j < NV; j++) {
        g_B[i * NV + j] = (i == j) ? 0.f : recs[i * 97 + j] * dri * sdr[j];
        g_A[i * NV + j] = (i == j) ? 0.f : adj[i * NV + j] * di * sd[j];
        g_D[i * NV + j] = di * sdr[j] / (fabsf(nfi2 - snfr[j]) + 1.f);
    }
    if (i == 0) g_scale[0] = __float_as_int(1.0f);
    if (i >= 1 && i < 64) g_scale[i] = 0;
}

// ---------- MPM persistent ----------
__device__ __forceinline__ void grid_barrier() {
    __syncthreads();
    if (threadIdx.x == 0) {
        __threadfence();
        unsigned long long t = atomicAdd(&g_bar, 1ULL);
        unsigned long long target = t - (t % (unsigned long long)gridDim.x)
                                    + (unsigned long long)gridDim.x;
        volatile unsigned long long* pc = &g_bar;
        while (*pc < target) { __nanosleep(32); }
        __threadfence();
    }
    __syncthreads();
}

__global__ void __launch_bounds__(96, 1) k_mpm() {
    __shared__ float Bs[NV * 97];
    __shared__ float As[NV], Ds[NV], xr[NV], red[3];
    int tid = threadIdx.x, bid = blockIdx.x;
    for (int idx = tid; idx < NNE; idx += NV) {
        int r = idx / NV, c = idx - r * NV;
        Bs[r * 97 + c] = g_B[idx];
    }
    As[tid] = g_A[bid * NV + tid];
    Ds[tid] = g_D[bid * NV + tid];
    xr[tid] = 1.f / 96.f;
    __syncthreads();
    volatile int* sc = g_scale;
    for (int it = 0; it < ITERS; it++) {
        int mb = it & 1;
        float xv = xr[tid];
        float m = 0.f;
#pragma unroll 8
        for (int b = 0; b < NV; b++) m = fmaxf(m, xr[b] * Bs[b * 97 + tid]);
        g_M[mb][bid * NV + tid] = m;
        grid_barrier();
        float sv = __int_as_float(sc[it]);
        float inv = (sv > 0.f) ? 1.f / sv : 1.f;
        float acc = xv * Ds[tid];
#pragma unroll 8
        for (int j = 0; j < NV; j++) acc += As[j] * __ldcg(&g_M[mb][j * NV + tid]);
        acc *= inv;
        xr[tid] = acc;
        float bm = acc;
        for (int off = 16; off; off >>= 1) bm = fmaxf(bm, __shfl_down_sync(0xffffffffu, bm, off));
        if ((tid & 31) == 0) red[tid >> 5] = bm;
        __syncthreads();
        if (tid == 0)
            atomicMax(&g_scale[it + 1], __float_as_int(fmaxf(red[0], fmaxf(red[1], red[2]))));
        __syncthreads();
    }
    g_xf[bid * NV + tid] = xr[tid];
}

// ---------- Hungarian (single warp, numpy-identical) ----------
__global__ void k_hung() {
    __shared__ float xf[NNE];
    __shared__ double u[97];
    __shared__ int p[97], way[97];
    __shared__ int cr[NV];
    int tid = threadIdx.x;  // 128
    for (int idx = tid; idx < NNE; idx += 128) xf[idx] = g_xf[idx];
    if (tid < 97) { u[tid] = 0.0; p[tid] = 0; way[tid] = 0; }
    __syncthreads();
    if (tid < 32) {
        int lane = tid;
        double vv0 = 0, vv1 = 0, vv2 = 0;
        for (int i = 1; i <= NV; i++) {
            if (lane == 0) p[0] = i;
            double mn0 = 1e18, mn1 = 1e18, mn2 = 1e18;
            bool us0 = false, us1 = false, us2 = false, usz = false;
            __syncwarp();
            int j0 = 0;
            while (true) {
                if (j0 == 0) { if (lane == 0) usz = true; }
                else {
                    int jj = j0 - 1;
                    if ((jj & 31) == lane) {
                        int c = jj >> 5;
                        if (c == 0) us0 = true; else if (c == 1) us1 = true; else us2 = true;
                    }
                }
                int i0 = p[j0];
                double ui0 = u[i0];
                const float* crow = &xf[(i0 - 1) * NV];
                double best = 1e18; int bestj = 0x7fffffff;
                if (!us0) {
                    int j = 1 + lane;
                    double cv = -(double)crow[j - 1] - ui0 - vv0;
                    if (cv < mn0) { mn0 = cv; way[j] = j0; }
                    if (mn0 < best) { best = mn0; bestj = j; }
                }
                if (!us1) {
                    int j = 33 + lane;
                    double cv = -(double)crow[j - 1] - ui0 - vv1;
                    if (cv < mn1) { mn1 = cv; way[j] = j0; }
                    if (mn1 < best) { best = mn1; bestj = j; }
                }
                if (!us2) {
                    int j = 65 + lane;
                    double cv = -(double)crow[j - 1] - ui0 - vv2;
                    if (cv < mn2) { mn2 = cv; way[j] = j0; }
                    if (mn2 < best) { best = mn2; bestj = j; }
                }
                for (int off = 16; off; off >>= 1) {
                    double ob = __shfl_down_sync(0xffffffffu, best, off);
                    int oj = __shfl_down_sync(0xffffffffu, bestj, off);
                    if (ob < best || (ob == best && oj < bestj)) { best = ob; bestj = oj; }
                }
                best = __shfl_sync(0xffffffffu, best, 0);
                bestj = __shfl_sync(0xffffffffu, bestj, 0);
                double delta = best; int j1 = bestj;
                __syncwarp();
                if (lane == 0 && usz) u[p[0]] += delta;
                if (us0) { u[p[1 + lane]]  += delta; vv0 -= delta; } else mn0 -= delta;
                if (us1) { u[p[33 + lane]] += delta; vv1 -= delta; } else mn1 -= delta;
                if (us2) { u[p[65 + lane]] += delta; vv2 -= delta; } else mn2 -= delta;
                __syncwarp();
                j0 = j1;
                if (p[j0] == 0) break;
            }
            if (lane == 0) {
                int jj = j0;
                while (jj) { int jn = way[jj]; p[jj] = p[jn]; jj = jn; }
            }
            __syncwarp();
        }
    }
    __syncthreads();
    if (tid < NV) cr[p[tid + 1] - 1] = tid;
    __syncthreads();
    if (tid < NV) g_ind[cr[tid]] = tid;
}

// ---------- final loss ----------
__global__ void k_final(const float* __restrict__ adj, float* __restrict__ out) {
    __shared__ int ind[NV];
    __shared__ float rb[8];
    int tid = threadIdx.x;
    if (tid < NV) ind[tid] = g_ind[tid];
    __syncthreads();
    float s = 0.f;
    for (int idx = tid; idx < OUTD; idx += 256) {
        int i = (int)((193.0 - sqrt(193.0 * 193.0 - 8.0 * (double)idx)) * 0.5);
        if (i < 0) i = 0; if (i > 95) i = 95;
        while (i > 0 && (i * (193 - i)) / 2 > idx) i--;
        while (i < 95 && ((i + 1) * (192 - i)) / 2 <= idx) i++;
        int j = i + idx - (i * (193 - i)) / 2;
        float a = adj[ind[i] * NV + ind[j]];
        float t = g_out[idx];
        s += fmaxf(a, 0.f) - a * t + log1pf(expf(-fabsf(a)));
    }
    float v = s;
    for (int off = 16; off; off >>= 1) v += __shfl_down_sync(0xffffffffu, v, off);
    if ((tid & 31) == 0) rb[tid >> 5] = v;
    __syncthreads();
    if (tid < 8) {
        v = rb[tid];
        for (int off = 4; off; off >>= 1) v += __shfl_down_sync(0xffu, v, off);
        if (tid == 0) out[0] = v / (float)OUTD + g_kl;
    }
}

extern "C" void kernel_launch(void* const* d_in, const int* in_sizes, int n_in,
                              void* d_out, int out_size) {
    const float* h   = (const float*)d_in[0];
    const float* adj = (const float*)d_in[1];
    const float* Wmu = (const float*)d_in[2];
    const float* bmu = (const float*)d_in[3];
    const float* Wls = (const float*)d_in[4];
    const float* bls = (const float*)d_in[5];
    const float* Wd1 = (const float*)d_in[6];
    const float* bd1 = (const float*)d_in[7];
    const float* Wd2 = (const float*)d_in[8];
    const float* bd2 = (const float*)d_in[9];
    float* out = (float*)d_out;

    dim3 g1(16, 2);
    k_gemv1<<<g1, 256>>>(h, Wmu, Wls);
    k_red1<<<1, 256>>>(bmu, bls);
    k_gemv2<<<16, 256>>>(h, Wd1);
    k_red2<<<1, 256>>>(bd1);
    k_out<<<19, 256>>>(Wd2, bd2);
    k_setup<<<1, 96>>>(adj);
    k_mpm<<<96, 96>>>();
    k_hung<<<1, 128>>>();
    k_final<<<1, 256>>>(adj, out);
}

// round 3
// speedup vs baseline: 1.7074x; 1.7074x over previous
#include <cuda_runtime.h>

#define NV 96
#define NNE 9216
#define LAT 256
#define OUTD 4656
#define ITERS 50

__device__ float g_p_mu[16][LAT];
__device__ float g_p_ls[16][LAT];
__device__ float g_p_y[16][LAT];
__device__ float g_out[OUTD];
__device__ float g_B[NNE];
__device__ float g_A[NNE];
__device__ float g_D[NNE];
__device__ float g_xf[NNE];
__device__ float g_M[2][NNE];
__device__ int   g_scale[64];
__device__ unsigned int g_arr[NV];   // monotonic barrier epochs, never reset
__device__ int   g_ind[NV];

// ---------------- GEMV stage 1: mu / ls partials ----------------
__global__ void k_gemv1(const float* __restrict__ h, const float* __restrict__ Wmu,
                        const float* __restrict__ Wls) {
    __shared__ float sh[576];
    int c = blockIdx.x, mat = blockIdx.y, o = threadIdx.x;
    int k0 = c * 576;
    for (int kk = o; kk < 576; kk += 256) sh[kk] = h[k0 + kk];
    __syncthreads();
    const float* Wp = (mat ? Wls : Wmu) + (size_t)k0 * LAT + o;
    float acc = 0.f;
#pragma unroll 4
    for (int kk = 0; kk < 576; kk++) acc += sh[kk] * Wp[(size_t)kk * LAT];
    if (mat) g_p_ls[c][o] = acc; else g_p_mu[c][o] = acc;
}

// ---------------- GEMV stage 2: y partials (mu folded in) ----------------
__global__ void k_gemv2(const float* __restrict__ h, const float* __restrict__ Wd1,
                        const float* __restrict__ bmu) {
    __shared__ float sh[592];
    int c = blockIdx.x, o = threadIdx.x;
    int k0 = c * 592;
    for (int kk = o; kk < 592; kk += 256) {
        int k = k0 + kk;
        float v;
        if (k < NNE) v = h[k];
        else {
            int oo = k - NNE;
            v = bmu[oo];
#pragma unroll
            for (int cc = 0; cc < 16; cc++) v += g_p_mu[cc][oo];
        }
        sh[kk] = v;
    }
    __syncthreads();
    const float* Wp = Wd1 + (size_t)k0 * LAT + o;
    float acc = 0.f;
#pragma unroll 4
    for (int kk = 0; kk < 592; kk++) acc += sh[kk] * Wp[(size_t)kk * LAT];
    g_p_y[c][o] = acc;
}

// ---------------- out = sigmoid(relu(y) @ Wd2 + b) ----------------
__global__ void k_out(const float* __restrict__ Wd2, const float* __restrict__ bd2,
                      const float* __restrict__ bd1) {
    __shared__ float ys[LAT];
    int t = threadIdx.x;
    {
        float s = bd1[t];
#pragma unroll
        for (int c = 0; c < 16; c++) s += g_p_y[c][t];
        ys[t] = fmaxf(s, 0.f);
    }
    __syncthreads();
    int o = blockIdx.x * 256 + t;
    if (o < OUTD) {
        float acc = bd2[o];
#pragma unroll 4
        for (int k = 0; k < LAT; k++) acc += ys[k] * Wd2[(size_t)k * OUTD + o];
        g_out[o] = 1.f / (1.f + expf(-acc));
    }
}

// ---------------- setup: A, B, D, scale ----------------
__global__ void k_setup(const float* __restrict__ adj) {
    __shared__ float recs[NV * 97];
    __shared__ float sd[NV], snf[NV], sdr[NV], snfr[NV];
    int i = threadIdx.x;  // 96
    float nfi = 0.f;
    for (int j = 0; j < NV; j++) nfi += adj[i * NV + j];
    sd[i] = adj[i * NV + i];
    snf[i] = nfi;
    float nfri = 0.f;
    for (int j = 0; j < NV; j++) {
        int a = min(i, j), b = max(i, j);
        float r = g_out[a * NV - (a * (a - 1)) / 2 + (b - a)];
        recs[i * 97 + j] = r;
        nfri += r;
    }
    sdr[i] = recs[i * 97 + i];
    snfr[i] = nfri;
    __syncthreads();
    float di = sd[i], dri = sdr[i], nfi2 = snf[i];
    for (int j = 0; j < NV; j++) {
        g_B[i * NV + j] = (i == j) ? 0.f : recs[i * 97 + j] * dri * sdr[j];
        g_A[i * NV + j] = (i == j) ? 0.f : adj[i * NV + j] * di * sd[j];
        g_D[i * NV + j] = di * sdr[j] / (fabsf(nfi2 - snfr[j]) + 1.f);
    }
    if (i == 0) g_scale[0] = __float_as_int(1.0f);
    if (i >= 1 && i < 64) g_scale[i] = 0;
}

// ---------------- MPM persistent: 96 CTAs x 96 threads ----------------
__global__ void __launch_bounds__(96, 1) k_mpm() {
    extern __shared__ float dyn[];
    float* Bs = dyn;                 // 96*97
    float* Ms = dyn + NV * 97;       // 96*96
    __shared__ float As[NV], Ds[NV], xr[NV], red[3];
    __shared__ unsigned sbase;
    int tid = threadIdx.x, bid = blockIdx.x;

    if (tid == 0) sbase = *(volatile unsigned*)&g_arr[bid];
    for (int idx = tid; idx < NNE; idx += NV) {
        int r = idx / NV, c = idx - r * NV;
        Bs[r * 97 + c] = g_B[idx];
    }
    As[tid] = g_A[bid * NV + tid];
    Ds[tid] = g_D[bid * NV + tid];
    xr[tid] = 1.f / 96.f;
    __syncthreads();
    unsigned base = sbase;

    for (int it = 0; it < ITERS; it++) {
        int mb = it & 1;
        float xv = xr[tid];
        float m = 0.f;
#pragma unroll 8
        for (int b = 0; b < NV; b++) m = fmaxf(m, xr[b] * Bs[b * 97 + tid]);
        __stcg(&g_M[mb][bid * NV + tid], m);
        // distributed grid barrier
        __syncthreads();
        unsigned tgt = base + (unsigned)(it + 1);
        if (tid == 0) { __threadfence(); *(volatile unsigned*)&g_arr[bid] = tgt; }
        {
            volatile unsigned* f = (volatile unsigned*)&g_arr[tid];
            while (*f < tgt) { }
        }
        __threadfence();
        __syncthreads();
        // stage M into shared
        {
            const float4* src = (const float4*)&g_M[mb][0];
            float4* dst = (float4*)Ms;
            for (int i4 = tid; i4 < NNE / 4; i4 += NV) dst[i4] = __ldcg(src + i4);
        }
        __syncthreads();
        float sv = __int_as_float(*(volatile int*)&g_scale[it]);
        float inv = (sv > 0.f) ? 1.f / sv : 1.f;
        float acc = xv * Ds[tid];
#pragma unroll 8
        for (int j = 0; j < NV; j++) acc += As[j] * Ms[j * NV + tid];
        acc *= inv;
        xr[tid] = acc;
        float bm = acc;
        for (int off = 16; off; off >>= 1) bm = fmaxf(bm, __shfl_down_sync(0xffffffffu, bm, off));
        if ((tid & 31) == 0) red[tid >> 5] = bm;
        __syncthreads();
        if (tid == 0)
            atomicMax(&g_scale[it + 1], __float_as_int(fmaxf(red[0], fmaxf(red[1], red[2]))));
    }
    __syncthreads();
    g_xf[bid * NV + tid] = xr[tid];
}

// ---------------- Hungarian: JV warm start + warp Dijkstra ----------------
__device__ __forceinline__ unsigned long long dmap(double x) {
    long long b = __double_as_longlong(x);
    return (unsigned long long)(b ^ ((b >> 63) | 0x8000000000000000LL));
}
__device__ __forceinline__ double dunmap(unsigned long long k) {
    long long b = (long long)k;
    b = b ^ (((~b) >> 63) | 0x8000000000000000LL);
    return __longlong_as_double(b);
}

__global__ void k_hung() {
    __shared__ float xf[NNE];
    __shared__ double u[97];
    __shared__ double vcol[97];
    __shared__ int p[97], way[97], rowof[97], rm[97];
    __shared__ int s_unm[NV];
    __shared__ int n_unm_s;
    int tid = threadIdx.x;  // 128
    for (int idx = tid; idx < NNE; idx += 128) xf[idx] = g_xf[idx];
    if (tid < 97) { u[tid] = 0.0; p[tid] = 0; way[tid] = 0; rm[tid] = 0; vcol[tid] = 0.0; }
    __syncthreads();
    // Phase A: column reduction v[j] = min_i c[i,j], first-argmin row
    if (tid < NV) {
        double best = 1e18; int bi = 1;
        for (int i2 = 0; i2 < NV; i2++) {
            double cv = -(double)xf[i2 * NV + tid];
            if (cv < best) { best = cv; bi = i2 + 1; }
        }
        vcol[tid + 1] = best;
        rowof[tid + 1] = bi;
    }
    __syncthreads();
    // Phase B: greedy assignment (serial, deterministic)
    if (tid == 0) {
        int cnt = 0;
        for (int j = 1; j <= NV; j++) {
            int i = rowof[j];
            if (!rm[i]) { rm[i] = 1; p[j] = i; }
        }
        for (int i = 1; i <= NV; i++) if (!rm[i]) s_unm[cnt++] = i;
        n_unm_s = cnt;
    }
    __syncthreads();
    // Phase C: augmenting Dijkstra per unmatched row (warp 0)
    if (tid < 32) {
        int lane = tid;
        const int J0 = 1 + lane, J1 = 33 + lane, J2 = 65 + lane;
        int nun = n_unm_s;
        for (int idx = 0; idx < nun; idx++) {
            int i = s_unm[idx];
            if (lane == 0) p[0] = i;
            double mn0 = 1e18, mn1 = 1e18, mn2 = 1e18;
            double vv0 = vcol[J0], vv1 = vcol[J1], vv2 = vcol[J2];
            bool us0 = false, us1 = false, us2 = false, usz = false;
            __syncwarp();
            int j0 = 0;
            while (true) {
                if (j0 == 0) { if (lane == 0) usz = true; }
                else if (j0 == J0) us0 = true;
                else if (j0 == J1) us1 = true;
                else if (j0 == J2) us2 = true;
                int i0 = p[j0];
                double ui0 = u[i0];
                const float* crow = &xf[(i0 - 1) * NV];
                unsigned long long k0 = ~0ULL, k1 = ~0ULL, k2 = ~0ULL;
                if (!us0) {
                    double cv = -(double)crow[J0 - 1] - ui0 - vv0;
                    if (cv < mn0) { mn0 = cv; way[J0] = j0; }
                    k0 = dmap(mn0);
                }
                if (!us1) {
                    double cv = -(double)crow[J1 - 1] - ui0 - vv1;
                    if (cv < mn1) { mn1 = cv; way[J1] = j0; }
                    k1 = dmap(mn1);
                }
                if (!us2) {
                    double cv = -(double)crow[J2 - 1] - ui0 - vv2;
                    if (cv < mn2) { mn2 = cv; way[J2] = j0; }
                    k2 = dmap(mn2);
                }
                unsigned long long lb = k0;
                if (k1 < lb) lb = k1;
                if (k2 < lb) lb = k2;
                unsigned hi = (unsigned)(lb >> 32);
                unsigned mh = __reduce_min_sync(0xffffffffu, hi);
                unsigned lo = (hi == mh) ? (unsigned)lb : 0xffffffffu;
                unsigned ml = __reduce_min_sync(0xffffffffu, lo);
                unsigned long long g = ((unsigned long long)mh << 32) | ml;
                double delta = dunmap(g);
                unsigned b0 = __ballot_sync(0xffffffffu, k0 == g);
                unsigned b1 = __ballot_sync(0xffffffffu, k1 == g);
                unsigned b2 = __ballot_sync(0xffffffffu, k2 == g);
                int j1 = b0 ? (__ffs(b0)) : (b1 ? (32 + __ffs(b1)) : (64 + __ffs(b2)));
                if (lane == 0 && usz) u[p[0]] += delta;
                if (us0) { u[p[J0]] += delta; vv0 -= delta; } else mn0 -= delta;
                if (us1) { u[p[J1]] += delta; vv1 -= delta; } else mn1 -= delta;
                if (us2) { u[p[J2]] += delta; vv2 -= delta; } else mn2 -= delta;
                __syncwarp();
                j0 = j1;
                if (p[j0] == 0) break;
            }
            if (lane == 0) {
                int jj = j0;
                while (jj) { int jn = way[jj]; p[jj] = p[jn]; jj = jn; }
            }
            if (us0) vcol[J0] = vv0;
            if (us1) vcol[J1] = vv1;
            if (us2) vcol[J2] = vv2;
            __syncwarp();
        }
    }
    __syncthreads();
    if (tid < NV) g_ind[tid] = p[tid + 1] - 1;
}

// ---------------- final: bce + kl ----------------
__global__ void k_final(const float* __restrict__ adj, const float* __restrict__ bmu,
                        const float* __restrict__ bls, float* __restrict__ out) {
    __shared__ int ind[NV];
    __shared__ float rb[8], rk[8];
    int tid = threadIdx.x;  // 256
    if (tid < NV) ind[tid] = g_ind[tid];
    // kl term for o = tid
    float klt;
    {
        float smu = bmu[tid], sls = bls[tid];
#pragma unroll
        for (int c = 0; c < 16; c++) { smu += g_p_mu[c][tid]; sls += g_p_ls[c][tid]; }
        klt = 1.f + sls - smu * smu - expf(sls);
    }
    __syncthreads();
    float s = 0.f;
    for (int idx = tid; idx < OUTD; idx += 256) {
        int i = (int)((193.0 - sqrt(193.0 * 193.0 - 8.0 * (double)idx)) * 0.5);
        if (i < 0) i = 0;
        if (i > 95) i = 95;
        while (i > 0 && (i * (193 - i)) / 2 > idx) i--;
        while (i < 95 && ((i + 1) * (192 - i)) / 2 <= idx) i++;
        int j = i + idx - (i * (193 - i)) / 2;
        float a = adj[ind[i] * NV + ind[j]];
        float t = g_out[idx];
        s += fmaxf(a, 0.f) - a * t + log1pf(expf(-fabsf(a)));
    }
    float v = s, w = klt;
    for (int off = 16; off; off >>= 1) {
        v += __shfl_down_sync(0xffffffffu, v, off);
        w += __shfl_down_sync(0xffffffffu, w, off);
    }
    if ((tid & 31) == 0) { rb[tid >> 5] = v; rk[tid >> 5] = w; }
    __syncthreads();
    if (tid < 8) {
        v = rb[tid]; w = rk[tid];
        for (int off = 4; off; off >>= 1) {
            v += __shfl_down_sync(0xffu, v, off);
            w += __shfl_down_sync(0xffu, w, off);
        }
        if (tid == 0) out[0] = v / (float)OUTD + (-0.5f * w / (float)NNE);
    }
}

extern "C" void kernel_launch(void* const* d_in, const int* in_sizes, int n_in,
                              void* d_out, int out_size) {
    const float* h   = (const float*)d_in[0];
    const float* adj = (const float*)d_in[1];
    const float* Wmu = (const float*)d_in[2];
    const float* bmu = (const float*)d_in[3];
    const float* Wls = (const float*)d_in[4];
    const float* bls = (const float*)d_in[5];
    const float* Wd1 = (const float*)d_in[6];
    const float* bd1 = (const float*)d_in[7];
    const float* Wd2 = (const float*)d_in[8];
    const float* bd2 = (const float*)d_in[9];
    float* out = (float*)d_out;

    static int smem_set = 0;
    if (!smem_set) {
        cudaFuncSetAttribute(k_mpm, cudaFuncAttributeMaxDynamicSharedMemorySize,
                             (NV * 97 + NNE) * 4);
        smem_set = 1;
    }

    dim3 g1(16, 2);
    k_gemv1<<<g1, 256>>>(h, Wmu, Wls);
    k_gemv2<<<16, 256>>>(h, Wd1, bmu);
    k_out<<<19, 256>>>(Wd2, bd2, bd1);
    k_setup<<<1, 96>>>(adj);
    k_mpm<<<96, 96, (NV * 97 + NNE) * 4>>>();
    k_hung<<<1, 128>>>();
    k_final<<<1, 256>>>(adj, bmu, bls, out);
}

// round 5
// speedup vs baseline: 3.8048x; 2.2285x over previous
#include <cuda_runtime.h>

#define NV 96
#define NNE 9216
#define LAT 256
#define OUTD 4656
#define ITERS 50
#define FULLW 0xffffffffu

__device__ float g_p_mu[16][LAT];
__device__ float g_p_ls[16][LAT];
__device__ float g_p_y[16][LAT];
__device__ float g_out[OUTD];
__device__ float g_xf[NNE];
__device__ float g_M[2][NNE];
__device__ int   g_scale[64];
__device__ unsigned g_arr[NV];     // monotonic barrier flags

// ---------------- MLP ----------------
__global__ void k_gemv1(const float* __restrict__ h, const float* __restrict__ Wmu,
                        const float* __restrict__ Wls) {
    __shared__ float sh[576];
    int c = blockIdx.x, mat = blockIdx.y, o = threadIdx.x;
    int k0 = c * 576;
    for (int kk = o; kk < 576; kk += 256) sh[kk] = h[k0 + kk];
    __syncthreads();
    const float* Wp = (mat ? Wls : Wmu) + (size_t)k0 * LAT + o;
    float acc = 0.f;
#pragma unroll 4
    for (int kk = 0; kk < 576; kk++) acc += sh[kk] * Wp[(size_t)kk * LAT];
    if (mat) g_p_ls[c][o] = acc; else g_p_mu[c][o] = acc;
}

__global__ void k_gemv2(const float* __restrict__ h, const float* __restrict__ Wd1,
                        const float* __restrict__ bmu) {
    __shared__ float sh[592];
    int c = blockIdx.x, o = threadIdx.x;
    int k0 = c * 592;
    for (int kk = o; kk < 592; kk += 256) {
        int k = k0 + kk;
        float v;
        if (k < NNE) v = h[k];
        else {
            int oo = k - NNE;
            v = bmu[oo];
#pragma unroll
            for (int cc = 0; cc < 16; cc++) v += g_p_mu[cc][oo];
        }
        sh[kk] = v;
    }
    __syncthreads();
    const float* Wp = Wd1 + (size_t)k0 * LAT + o;
    float acc = 0.f;
#pragma unroll 4
    for (int kk = 0; kk < 592; kk++) acc += sh[kk] * Wp[(size_t)kk * LAT];
    g_p_y[c][o] = acc;
}

__global__ void k_out(const float* __restrict__ Wd2, const float* __restrict__ bd2,
                      const float* __restrict__ bd1) {
    __shared__ float ys[LAT];
    int t = threadIdx.x;
    {
        float s = bd1[t];
#pragma unroll
        for (int c = 0; c < 16; c++) s += g_p_y[c][t];
        ys[t] = fmaxf(s, 0.f);
    }
    __syncthreads();
    int o = blockIdx.x * 256 + t;
    if (o < OUTD) {
        float acc = bd2[o];
#pragma unroll 4
        for (int k = 0; k < LAT; k++) acc += ys[k] * Wd2[(size_t)k * OUTD + o];
        g_out[o] = 1.f / (1.f + expf(-acc));
    }
}

// ---------------- helpers ----------------
__device__ __forceinline__ int triidx(int a, int b) {
    return a * NV - (a * (a - 1)) / 2 + (b - a);
}
__device__ __forceinline__ float rec_of(int i, int j) {
    int a = min(i, j), b = max(i, j);
    return g_out[triidx(a, b)];
}
__device__ __forceinline__ unsigned fmap(float x) {
    unsigned b = __float_as_uint(x);
    return b ^ ((unsigned)(((int)b) >> 31) | 0x80000000u);
}
__device__ __forceinline__ float funmap(unsigned k) {
    return __uint_as_float((k & 0x80000000u) ? (k ^ 0x80000000u) : ~k);
}

// ---------------- mega persistent kernel: setup + MPM + hung + loss ----------------
__global__ void __launch_bounds__(96, 1) k_mega(const float* __restrict__ adj,
                                                const float* __restrict__ bmu,
                                                const float* __restrict__ bls,
                                                float* __restrict__ out) {
    extern __shared__ float dyn[];
    float* Bs = dyn;               // 96*97
    float* Ms = dyn + NV * 97;     // 9216 (reused as xf in hung)
    __shared__ float sd[NV], snf[NV], sdr[NV], snfr[NV];
    __shared__ float As[NV], Ds[NV], xr[NV];
    __shared__ float red[3], redk[3];
    __shared__ float u_[97], vcol[97];
    __shared__ int p_[97], way_[97], rowof_[97], fl[NV];
    __shared__ int indsh[NV];
    __shared__ int sn0;
    __shared__ unsigned sbase;

    int tid = threadIdx.x, bid = blockIdx.x;
    if (tid == 0) sbase = *(volatile unsigned*)&g_arr[bid];

    // ---- setup (per-CTA local) ----
    {
        float drt = 0.f, nfrt = 0.f;
        for (int i = 0; i < NV; i++) {
            float r = rec_of(i, tid);
            nfrt += r;
            if (i == tid) drt = r;
        }
        sdr[tid] = drt;
        snfr[tid] = nfrt;
        float nft = 0.f;
        const float* arow = adj + tid * NV;
        for (int j = 0; j < NV; j++) nft += arow[j];
        sd[tid] = arow[tid];
        snf[tid] = nft;
    }
    __syncthreads();
    {
        float drt = sdr[tid];
        for (int i = 0; i < NV; i++)
            Bs[i * 97 + tid] = (i == tid) ? 0.f : rec_of(i, tid) * sdr[i] * drt;
        As[tid] = (bid == tid) ? 0.f : adj[bid * NV + tid] * sd[bid] * sd[tid];
        Ds[tid] = sd[bid] * sdr[tid] / (fabsf(snf[bid] - snfr[tid]) + 1.f);
        xr[tid] = 1.f / 96.f;
    }
    __syncthreads();
    unsigned base = sbase;

    // ---- MPM ----
    for (int it = 0; it < ITERS; it++) {
        int mb = it & 1;
        float xv = xr[tid];
        float m0 = 0.f, m1 = 0.f, m2 = 0.f, m3 = 0.f;
#pragma unroll
        for (int b = 0; b < NV; b += 4) {
            m0 = fmaxf(m0, xr[b] * Bs[b * 97 + tid]);
            m1 = fmaxf(m1, xr[b + 1] * Bs[(b + 1) * 97 + tid]);
            m2 = fmaxf(m2, xr[b + 2] * Bs[(b + 2) * 97 + tid]);
            m3 = fmaxf(m3, xr[b + 3] * Bs[(b + 3) * 97 + tid]);
        }
        __stcg(&g_M[mb][bid * NV + tid], fmaxf(fmaxf(m0, m1), fmaxf(m2, m3)));
        // grid barrier
        __syncthreads();
        unsigned tgt = base + (unsigned)(it + 1);
        if (tid == 0) { __threadfence(); *(volatile unsigned*)&g_arr[bid] = tgt; }
        {
            volatile unsigned* f = (volatile unsigned*)&g_arr[tid];
            while (*f < tgt) { }
        }
        __threadfence();
        __syncthreads();
        // stage M
        {
            const float4* src = (const float4*)&g_M[mb][0];
            float4* dst = (float4*)Ms;
            for (int i4 = tid; i4 < NNE / 4; i4 += NV) dst[i4] = __ldcg(src + i4);
        }
        __syncthreads();
        float sv = __int_as_float(*(volatile int*)&g_scale[it]);
        float inv = (sv > 0.f) ? 1.f / sv : 1.f;
        float a0 = xv * Ds[tid], a1 = 0.f, a2 = 0.f, a3 = 0.f;
#pragma unroll
        for (int j = 0; j < NV; j += 4) {
            a0 += As[j] * Ms[j * NV + tid];
            a1 += As[j + 1] * Ms[(j + 1) * NV + tid];
            a2 += As[j + 2] * Ms[(j + 2) * NV + tid];
            a3 += As[j + 3] * Ms[(j + 3) * NV + tid];
        }
        float acc = ((a0 + a1) + (a2 + a3)) * inv;
        xr[tid] = acc;
        float bm = acc;
        for (int off = 16; off; off >>= 1) bm = fmaxf(bm, __shfl_down_sync(FULLW, bm, off));
        if ((tid & 31) == 0) red[tid >> 5] = bm;
        __syncthreads();
        if (tid == 0)
            atomicMax(&g_scale[it + 1], __float_as_int(fmaxf(red[0], fmaxf(red[1], red[2]))));
    }
    __syncthreads();
    g_xf[bid * NV + tid] = xr[tid];
    // final barrier before hung
    {
        __syncthreads();
        unsigned tgt = base + (unsigned)(ITERS + 1);
        if (tid == 0) { __threadfence(); *(volatile unsigned*)&g_arr[bid] = tgt; }
        volatile unsigned* f = (volatile unsigned*)&g_arr[tid];
        while (*f < tgt) { }
        __threadfence();
        __syncthreads();
    }
    if (bid != 0) return;

    // ======== CTA 0: Hungarian fp32, R3-validated warm start + Dijkstra ========
    float* xf = Ms;
    for (int idx = tid; idx < NNE; idx += NV) xf[idx] = __ldcg(&g_xf[idx]);
    if (tid < 97) { u_[tid] = 0.f; p_[tid] = 0; way_[tid] = 0; rowof_[tid] = 0; }
    __syncthreads();
    // Phase A: column reduction v[j] = min_i c[i,j], first-argmin row
    if (tid < NV) {
        float best = 1e30f; int bi = 1;
        for (int i2 = 0; i2 < NV; i2++) {
            float cv = -xf[i2 * NV + tid];
            if (cv < best) { best = cv; bi = i2 + 1; }
        }
        vcol[tid + 1] = best;
        rowof_[tid + 1] = bi;
    }
    __syncthreads();
    // Phase B: greedy assignment (serial, deterministic); way_ reused as rowmark
    if (tid == 0) {
        int cnt = 0;
        for (int j = 1; j <= NV; j++) {
            int i = rowof_[j];
            if (way_[i] == 0) { way_[i] = 1; p_[j] = i; }
        }
        for (int i = 1; i <= NV; i++) if (way_[i] == 0) fl[cnt++] = i;
        for (int i = 0; i <= NV; i++) way_[i] = 0;
        sn0 = cnt;
    }
    __syncthreads();
    // Phase C: augmenting Dijkstra per free row (warp 0)
    if (tid < 32) {
        int lane = tid;
        const int J0 = 1 + lane, J1 = 33 + lane, J2 = 65 + lane;
        int nf = sn0;
        for (int idx = 0; idx < nf; idx++) {
            int i = fl[idx];
            if (lane == 0) p_[0] = i;
            float mn0 = 1e30f, mn1 = 1e30f, mn2 = 1e30f;
            float vv0 = vcol[J0], vv1 = vcol[J1], vv2 = vcol[J2];
            bool us0 = false, us1 = false, us2 = false, usz = false;
            __syncwarp();
            int j0 = 0;
            while (true) {
                if (j0 == 0) { if (lane == 0) usz = true; }
                else if (j0 == J0) us0 = true;
                else if (j0 == J1) us1 = true;
                else if (j0 == J2) us2 = true;
                int i0 = p_[j0];
                float ui0 = u_[i0];
                const float* crow = &xf[(i0 - 1) * NV];
                unsigned k0 = ~0u, k1 = ~0u, k2 = ~0u;
                if (!us0) {
                    float cv = -crow[J0 - 1] - ui0 - vv0;
                    if (cv < mn0) { mn0 = cv; way_[J0] = j0; }
                    k0 = fmap(mn0);
                }
                if (!us1) {
                    float cv = -crow[J1 - 1] - ui0 - vv1;
                    if (cv < mn1) { mn1 = cv; way_[J1] = j0; }
                    k1 = fmap(mn1);
                }
                if (!us2) {
                    float cv = -crow[J2 - 1] - ui0 - vv2;
                    if (cv < mn2) { mn2 = cv; way_[J2] = j0; }
                    k2 = fmap(mn2);
                }
                unsigned lb = min(k0, min(k1, k2));
                unsigned g = __reduce_min_sync(FULLW, lb);
                float delta = funmap(g);
                unsigned b0 = __ballot_sync(FULLW, k0 == g);
                unsigned b1 = __ballot_sync(FULLW, k1 == g);
                unsigned b2 = __ballot_sync(FULLW, k2 == g);
                int j1s = b0 ? __ffs(b0) : (b1 ? 32 + __ffs(b1) : 64 + __ffs(b2));
                if (lane == 0 && usz) u_[p_[0]] += delta;
                if (us0) { u_[p_[J0]] += delta; vv0 -= delta; } else mn0 -= delta;
                if (us1) { u_[p_[J1]] += delta; vv1 -= delta; } else mn1 -= delta;
                if (us2) { u_[p_[J2]] += delta; vv2 -= delta; } else mn2 -= delta;
                __syncwarp();
                j0 = j1s;
                if (p_[j0] == 0) break;
            }
            if (lane == 0) {
                int jj = j0;
                while (jj) { int jn = way_[jj]; p_[jj] = p_[jn]; jj = jn; }
            }
            if (us0) vcol[J0] = vv0;
            if (us1) vcol[J1] = vv1;
            if (us2) vcol[J2] = vv2;
            __syncwarp();
        }
    }
    __syncthreads();
    if (tid < NV) indsh[tid] = p_[tid + 1] - 1;
    __syncthreads();

    // ---- final loss ----
    float s = 0.f;
    for (int idx = tid; idx < OUTD; idx += NV) {
        int i = (int)((193.0 - sqrt(193.0 * 193.0 - 8.0 * (double)idx)) * 0.5);
        if (i < 0) i = 0;
        if (i > 95) i = 95;
        while (i > 0 && (i * (193 - i)) / 2 > idx) i--;
        while (i < 95 && ((i + 1) * (192 - i)) / 2 <= idx) i++;
        int j = i + idx - (i * (193 - i)) / 2;
        float a = adj[indsh[i] * NV + indsh[j]];
        float t = g_out[idx];
        s += fmaxf(a, 0.f) - a * t + log1pf(expf(-fabsf(a)));
    }
    float w = 0.f;
    for (int o = tid; o < LAT; o += NV) {
        float smu = bmu[o], sls = bls[o];
#pragma unroll
        for (int c = 0; c < 16; c++) { smu += g_p_mu[c][o]; sls += g_p_ls[c][o]; }
        w += 1.f + sls - smu * smu - expf(sls);
    }
    for (int off = 16; off; off >>= 1) {
        s += __shfl_down_sync(FULLW, s, off);
        w += __shfl_down_sync(FULLW, w, off);
    }
    if ((tid & 31) == 0) { red[tid >> 5] = s; redk[tid >> 5] = w; }
    __syncthreads();
    if (tid == 0) {
        float S = red[0] + red[1] + red[2];
        float W = redk[0] + redk[1] + redk[2];
        out[0] = S / (float)OUTD + (-0.5f * W / (float)NNE);
    }
}

extern "C" void kernel_launch(void* const* d_in, const int* in_sizes, int n_in,
                              void* d_out, int out_size) {
    const float* h   = (const float*)d_in[0];
    const float* adj = (const float*)d_in[1];
    const float* Wmu = (const float*)d_in[2];
    const float* bmu = (const float*)d_in[3];
    const float* Wls = (const float*)d_in[4];
    const float* bls = (const float*)d_in[5];
    const float* Wd1 = (const float*)d_in[6];
    const float* bd1 = (const float*)d_in[7];
    const float* Wd2 = (const float*)d_in[8];
    const float* bd2 = (const float*)d_in[9];
    float* out = (float*)d_out;

    static int smem_set = 0;
    if (!smem_set) {
        cudaFuncSetAttribute(k_mega, cudaFuncAttributeMaxDynamicSharedMemorySize,
                             (NV * 97 + NNE) * 4);
        smem_set = 1;
    }

    dim3 g1(16, 2);
    k_gemv1<<<g1, 256>>>(h, Wmu, Wls);
    k_gemv2<<<16, 256>>>(h, Wd1, bmu);
    k_out<<<19, 256>>>(Wd2, bd2, bd1);
    k_mega<<<96, 96, (NV * 97 + NNE) * 4>>>(adj, bmu, bls, out);
}